// round 15
// baseline (speedup 1.0000x reference)
#include <cuda_runtime.h>
#include <cuda_fp16.h>
#include <cstdint>

// ======================= problem constants =======================

static constexpr int M = 128;
static constexpr int K = 4096;
static constexpr int N = 11008;
static constexpr int MTILE = 64;            // output rows per CTA
static constexpr int NTILE = 128;           // output columns per CTA
static constexpr int KTILE = 64;            // K per pipeline stage
static constexpr int KSPLIT = 3;            // uneven K thirds: 22/22/20 stages
static constexpr int THREADS = 256;         // 8 warps (2m x 4n), warp tile 32x32
static constexpr int NBLK_N = N / NTILE;    // 86
static constexpr int NBLK_M = M / MTILE;    // 2

// SMEM (dynamic): A fp16 2 x 8KB ; B fp16 2 x 16KB = 48KB
static constexpr uint32_t A_BUF_STRIDE = 8192;    // 64 m x 64 k fp16
static constexpr uint32_t B_BASE_OFF   = 16384;
static constexpr uint32_t B_BUF_STRIDE = 16384;   // 128 n x 64 k fp16
static constexpr uint32_t SMEM_BYTES   = 49152 + 1024;

// fp16 copy of x with k-chunk permutation {0,4,1,5,2,6,3,7} baked in
// (matches the lop3 dual-nibble extraction order of the B dequant path).
__device__ __half g_x16[M * K];

// ======================= small helpers =======================

__device__ __forceinline__ uint32_t smem_u32(const void* p) {
    uint32_t a;
    asm("{ .reg .u64 t; cvta.to.shared.u64 t, %1; cvt.u32.u64 %0, t; }"
        : "=r"(a) : "l"(p));
    return a;
}

// SW128 swizzle (Swizzle<3,4,3>): XOR bits [6:4] with bits [9:7]
#define SWZ(x) ((uint32_t)(x) ^ ((((uint32_t)(x)) >> 3) & 0x70u))

#define STS128(smem_addr, r0, r1, r2, r3) \
    asm volatile( \
        "st.shared.v4.b32 [%0], {%1, %2, %3, %4};" \
        :: "r"(smem_addr), "r"(r0), "r"(r1), "r"(r2), "r"(r3) \
        : "memory")

#define CP_ASYNC16(dst, src) \
    asm volatile("cp.async.ca.shared.global [%0], [%1], 16;" \
                 :: "r"(dst), "l"(src) : "memory")

#define CP_COMMIT()  asm volatile("cp.async.commit_group;" ::: "memory")
#define CP_WAIT0()   asm volatile("cp.async.wait_group 0;" ::: "memory")

// d = (a & 0x000F000F) | 0x64006400  -> fp16x2 (1024+q_lo, 1024+q_hi)
__device__ __forceinline__ uint32_t lop3_nib(uint32_t a) {
    uint32_t d;
    asm("lop3.b32 %0, %1, 0x000F000F, 0x64006400, 0xEA;" : "=r"(d) : "r"(a));
    return d;
}

__device__ __forceinline__ void ldsm4(uint32_t (&r)[4], uint32_t addr) {
    asm volatile(
        "ldmatrix.sync.aligned.m8n8.x4.shared.b16 {%0,%1,%2,%3}, [%4];"
        : "=r"(r[0]), "=r"(r[1]), "=r"(r[2]), "=r"(r[3])
        : "r"(addr));
}

__device__ __forceinline__ void mma16816(float (&c)[4], const uint32_t (&a)[4],
                                         uint32_t b0, uint32_t b1) {
    asm volatile(
        "mma.sync.aligned.m16n8k16.row.col.f32.f16.f16.f32 "
        "{%0,%1,%2,%3}, {%4,%5,%6,%7}, {%8,%9}, {%0,%1,%2,%3};"
        : "+f"(c[0]), "+f"(c[1]), "+f"(c[2]), "+f"(c[3])
        : "r"(a[0]), "r"(a[1]), "r"(a[2]), "r"(a[3]), "r"(b0), "r"(b1));
}

// ============ kernel 0: fused  x fp32->fp16 (k-permuted)  +  out=bias ============
// 4x ILP per thread (the old version was MLP=1 latency-bound).

static constexpr int CONV_BLOCKS = (M * K / 8) / (256 * 4);          // 64
static constexpr int INIT_BLOCKS = (M * N / 4 + 256 * 4 - 1) / (256 * 4); // 344

__global__ void prep_kernel(const float* __restrict__ x,
                            const float* __restrict__ bias,
                            float* __restrict__ out) {
    const int b = blockIdx.x;
    if (b < CONV_BLOCKS) {
        const int base = (b * 256 + threadIdx.x) * 4;   // 4 chunks of 8 floats
        float4 v[8];
        #pragma unroll
        for (int j = 0; j < 4; ++j) {
            const float4* s =
                reinterpret_cast<const float4*>(x) + (size_t)(base + j) * 2;
            v[2 * j]     = s[0];
            v[2 * j + 1] = s[1];
        }
        #pragma unroll
        for (int j = 0; j < 4; ++j) {
            uint4 o;
            __half2* o2 = reinterpret_cast<__half2*>(&o);
            o2[0] = __floats2half2_rn(v[2 * j].x, v[2 * j + 1].x);   // k 0,4
            o2[1] = __floats2half2_rn(v[2 * j].y, v[2 * j + 1].y);   // k 1,5
            o2[2] = __floats2half2_rn(v[2 * j].z, v[2 * j + 1].z);   // k 2,6
            o2[3] = __floats2half2_rn(v[2 * j].w, v[2 * j + 1].w);   // k 3,7
            reinterpret_cast<uint4*>(g_x16)[base + j] = o;
        }
    } else {
        const int base = ((b - CONV_BLOCKS) * 256 + threadIdx.x) * 4;
        #pragma unroll
        for (int j = 0; j < 4; ++j) {
            const int i = base + j;
            if (i < M * N / 4) {
                const float4 bv =
                    reinterpret_cast<const float4*>(bias)[i % (N / 4)];
                reinterpret_cast<float4*>(out)[i] = bv;
            }
        }
    }
}

// ======================= kernel 1: fused dequant + GEMM =======================
//
// CTA tile 64(m) x 128(n); 8 warps (2m x 4n), warp tile 32x32 (C = 32 regs ->
// ~70 regs/thread -> 3 CTAs/SM -> 24 warps/SM = 6 per SMSP, vs 4 before).
// A: [64 m][64 k] fp16 SW128 (k-permuted), cp.async, double-buffered.
// B: [128 n][64 k] fp16 SW128, lop3-dequantized (one n-column per thread
//    pair), double-buffered. Same producer scheme as the r12 best.
// K split {22,22,20} stages (boundaries multiples of GS=128).
// Grid 86 x 2 x 3 = 516 CTAs. Epilogue atomicAdd onto bias-preloaded out.

__global__ void __launch_bounds__(THREADS, 3)
quantlinear_kernel(
    const int*   __restrict__ qweight,  // [K/8, N] int32 (8 nibbles along K)
    const int*   __restrict__ qzeros,   // [G, N/8] int32 (8 nibbles along N)
    const float* __restrict__ scales,   // [G, N]
    float*       __restrict__ out       // [M, N], preloaded with bias
) {
    extern __shared__ __align__(1024) char smem_raw[];
    const uint32_t sb = (smem_u32(smem_raw) + 1023u) & ~1023u;

    const int tid  = threadIdx.x;
    const int wid  = tid >> 5;
    const int lane = tid & 31;
    const int mw   = wid >> 2;   // warp m index (0..1) -> rows mw*32
    const int nw   = wid & 3;    // warp n index (0..3) -> cols nw*32
    const int n0   = blockIdx.x * NTILE;
    const int m0   = blockIdx.y * MTILE;
    const int kz   = blockIdx.z;

    // uneven K split: stage starts {0,22,44}, counts {22,22,20}
    const int stage0 = kz * 22;
    const int nst    = (kz == 2) ? 20 : 22;
    const int qrow0  = stage0 * 8;               // first packed qweight row
    const int g0     = stage0 >> 1;              // first quant group
    const int kbase0 = stage0 * KTILE;

    // ldmatrix per-thread invariant (unswizzled) byte offsets
    // A: warp rows mw*32 + (lane&15), +16 rows for second frag (+2048B)
    const uint32_t aOff0 =
        (uint32_t)((mw * 32 + (lane & 15)) * 128 + (lane >> 4) * 16);
    // B: warp cols nw*32; x4 tile covers 16 n; second at +2048B
    const uint32_t bOff0 =
        (uint32_t)((nw * 32 + ((lane >> 4) << 3) + (lane & 7)) * 128 +
                   ((lane >> 3) & 1) * 16);

    // B loader: thread pair owns one n-column, 4 packed k-rows each
    const int lnB = tid >> 1;        // 0..127
    const int krB = tid & 1;         // packed-row parity; rows krB + 2*j
    const int gn  = n0 + lnB;

    float c[2][4][4];   // [mi 16m][j = 2*sub+p][frag]
    #pragma unroll
    for (int i = 0; i < 2; ++i)
        #pragma unroll
        for (int j = 0; j < 4; ++j)
            #pragma unroll
            for (int l = 0; l < 4; ++l) c[i][j][l] = 0.f;

    uint32_t bw[4];
    __half2  s2, z2;

    // ---- stage helpers ----

    auto ISSUE_A = [&](int t, int buf) {
        const uint32_t abase = sb + (uint32_t)buf * A_BUF_STRIDE;
        const int kbase = kbase0 + t * KTILE;
        #pragma unroll
        for (int i = 0; i < 2; ++i) {
            const int cidx = tid + THREADS * i;   // 0..511
            const int m  = cidx >> 3;             // 0..63
            const int ck = cidx & 7;              // 16B chunk in 128B row
            const uint32_t off = SWZ((uint32_t)(m * 128 + ck * 16));
            const __half* src = g_x16 + (size_t)(m0 + m) * K + kbase + ck * 8;
            CP_ASYNC16(abase + off, src);
        }
        CP_COMMIT();
    };

    auto LOAD_B = [&](int t) {
        if ((t & 1) == 0) {   // new quant group every 2 stages (GS=128)
            const int g = g0 + (t >> 1);
            const float s = scales[(size_t)g * N + gn];
            const uint32_t zw = (uint32_t)qzeros[(size_t)g * (N / 8) + (gn >> 3)];
            const uint32_t z = ((zw >> ((gn & 7) * 4)) & 0xFu) + 1u;
            s2 = __float2half2_rn(s);
            uint32_t zb = 0x64006400u + z + (z << 16);   // fp16x2 (1024+z), exact
            z2 = *reinterpret_cast<__half2*>(&zb);
        }
        #pragma unroll
        for (int j = 0; j < 4; ++j) {
            const int r = krB + 2 * j;            // packed k-row 0..7
            bw[j] = (uint32_t)qweight[(size_t)(qrow0 + t * 8 + r) * N + gn];
        }
    };

    auto DEQ_STS = [&](int buf) {
        const uint32_t bbase = sb + B_BASE_OFF + (uint32_t)buf * B_BUF_STRIDE;
        #pragma unroll
        for (int j = 0; j < 4; ++j) {
            const int r = krB + 2 * j;
            const uint32_t w = bw[j];
            uint32_t o[4];
            // dual-nibble: pairs (k0,k4),(k1,k5),(k2,k6),(k3,k7) — matches
            // the permuted A layout.
            o[0] = lop3_nib(w);
            o[1] = lop3_nib(w >> 4);
            o[2] = lop3_nib(w >> 8);
            o[3] = lop3_nib(w >> 12);
            #pragma unroll
            for (int i = 0; i < 4; ++i) {
                __half2 q2 = *reinterpret_cast<__half2*>(&o[i]);
                __half2 w2 = __hmul2(__hsub2(q2, z2), s2);  // (q-z) exact
                o[i] = *reinterpret_cast<uint32_t*>(&w2);
            }
            const uint32_t off = SWZ((uint32_t)(lnB * 128 + r * 16));
            STS128(bbase + off, o[0], o[1], o[2], o[3]);
        }
    };

    auto COMPUTE = [&](int buf) {
        const uint32_t abase = sb + (uint32_t)buf * A_BUF_STRIDE;
        const uint32_t bbase = sb + B_BASE_OFF + (uint32_t)buf * B_BUF_STRIDE;
        #pragma unroll
        for (int ks = 0; ks < 4; ++ks) {
            const uint32_t akb = (uint32_t)(ks * 32);
            uint32_t a[2][4];
            ldsm4(a[0], abase + SWZ(aOff0 + akb));
            ldsm4(a[1], abase + SWZ(aOff0 + 2048 + akb));   // +16 m rows
            #pragma unroll
            for (int sub = 0; sub < 2; ++sub) {
                uint32_t b[4];
                ldsm4(b, bbase + SWZ(bOff0 + (uint32_t)(sub * 2048) + akb));
                #pragma unroll
                for (int mi = 0; mi < 2; ++mi) {
                    mma16816(c[mi][2 * sub + 0], a[mi], b[0], b[1]);
                    mma16816(c[mi][2 * sub + 1], a[mi], b[2], b[3]);
                }
            }
        }
    };

    // -------- pipeline --------
    ISSUE_A(0, 0);
    LOAD_B(0);
    DEQ_STS(0);
    CP_WAIT0();
    __syncthreads();

    for (int t = 0; t < nst; ++t) {
        const int cur = t & 1;
        if (t + 1 < nst) {
            ISSUE_A(t + 1, cur ^ 1);
            LOAD_B(t + 1);
        }
        COMPUTE(cur);
        if (t + 1 < nst) {
            DEQ_STS(cur ^ 1);
            CP_WAIT0();
        }
        __syncthreads();
    }

    // -------- epilogue: atomic accumulate into out (bias preloaded) --------
    const int q  = lane >> 2;
    const int r2 = lane & 3;
    #pragma unroll
    for (int mi = 0; mi < 2; ++mi) {
        const int row0 = m0 + mw * 32 + mi * 16 + q;
        #pragma unroll
        for (int j = 0; j < 4; ++j) {
            const int col = n0 + nw * 32 + (j >> 1) * 16 + (j & 1) * 8 + 2 * r2;
            float* p0 = out + (size_t)row0 * N + col;
            float* p1 = out + (size_t)(row0 + 8) * N + col;
            atomicAdd(p0,     c[mi][j][0]);
            atomicAdd(p0 + 1, c[mi][j][1]);
            atomicAdd(p1,     c[mi][j][2]);
            atomicAdd(p1 + 1, c[mi][j][3]);
        }
    }
}

// ======================= launch =======================

extern "C" void kernel_launch(void* const* d_in, const int* in_sizes, int n_in,
                              void* d_out, int out_size) {
    const float* x       = (const float*)d_in[0];
    const int*   qweight = (const int*)d_in[1];
    const int*   qzeros  = (const int*)d_in[2];
    const float* scales  = (const float*)d_in[3];
    const float* bias    = (const float*)d_in[4];
    // d_in[5] = g_idx: arange(K)//128 for this problem; group = k/GS hardcoded.
    float* out = (float*)d_out;

    cudaFuncSetAttribute(quantlinear_kernel,
                         cudaFuncAttributeMaxDynamicSharedMemorySize, SMEM_BYTES);

    prep_kernel<<<CONV_BLOCKS + INIT_BLOCKS, 256>>>(x, bias, out);
    dim3 grid(NBLK_N, NBLK_M, KSPLIT);
    quantlinear_kernel<<<grid, THREADS, SMEM_BYTES>>>(qweight, qzeros, scales, out);
}

// round 16
// speedup vs baseline: 1.2100x; 1.2100x over previous
#include <cuda_runtime.h>
#include <cuda_fp16.h>
#include <cstdint>

// ======================= problem constants =======================

static constexpr int M = 128;
static constexpr int K = 4096;
static constexpr int N = 11008;
static constexpr int NTILE = 256;           // output columns per CTA
static constexpr int KTILE = 64;            // K per pipeline stage
static constexpr int KSPLIT = 3;            // uneven K thirds: 22/22/20 stages
static constexpr int THREADS = 256;         // 8 warps (2m x 4n), warp tile 64x64
static constexpr int NBLK_N = N / NTILE;    // 43

// SMEM (dynamic): A fp16 2 x 16KB ; B fp16 2 x 32KB = 96KB
static constexpr uint32_t A_BUF_STRIDE = 16384;   // 128 m x 64 k fp16
static constexpr uint32_t B_BASE_OFF   = 32768;
static constexpr uint32_t B_BUF_STRIDE = 32768;   // 256 n x 64 k fp16
static constexpr uint32_t SMEM_BYTES   = 98304 + 1024;

// fp16 copy of x with k-chunk permutation {0,4,1,5,2,6,3,7} baked in
// (matches the lop3 dual-nibble extraction order of the B dequant path).
__device__ __half g_x16[M * K];

// ======================= small helpers =======================

__device__ __forceinline__ uint32_t smem_u32(const void* p) {
    uint32_t a;
    asm("{ .reg .u64 t; cvta.to.shared.u64 t, %1; cvt.u32.u64 %0, t; }"
        : "=r"(a) : "l"(p));
    return a;
}

// SW128 swizzle (Swizzle<3,4,3>): XOR bits [6:4] with bits [9:7]
#define SWZ(x) ((uint32_t)(x) ^ ((((uint32_t)(x)) >> 3) & 0x70u))

#define STS128(smem_addr, r0, r1, r2, r3) \
    asm volatile( \
        "st.shared.v4.b32 [%0], {%1, %2, %3, %4};" \
        :: "r"(smem_addr), "r"(r0), "r"(r1), "r"(r2), "r"(r3) \
        : "memory")

#define CP_ASYNC16(dst, src) \
    asm volatile("cp.async.ca.shared.global [%0], [%1], 16;" \
                 :: "r"(dst), "l"(src) : "memory")

#define CP_COMMIT()  asm volatile("cp.async.commit_group;" ::: "memory")
#define CP_WAIT0()   asm volatile("cp.async.wait_group 0;" ::: "memory")

// d = (a & 0x000F000F) | 0x64006400  -> fp16x2 (1024+q_lo, 1024+q_hi)
__device__ __forceinline__ uint32_t lop3_nib(uint32_t a) {
    uint32_t d;
    asm("lop3.b32 %0, %1, 0x000F000F, 0x64006400, 0xEA;" : "=r"(d) : "r"(a));
    return d;
}

__device__ __forceinline__ void ldsm4(uint32_t (&r)[4], uint32_t addr) {
    asm volatile(
        "ldmatrix.sync.aligned.m8n8.x4.shared.b16 {%0,%1,%2,%3}, [%4];"
        : "=r"(r[0]), "=r"(r[1]), "=r"(r[2]), "=r"(r[3])
        : "r"(addr));
}

__device__ __forceinline__ void mma16816(float (&c)[4], const uint32_t (&a)[4],
                                         uint32_t b0, uint32_t b1) {
    asm volatile(
        "mma.sync.aligned.m16n8k16.row.col.f32.f16.f16.f32 "
        "{%0,%1,%2,%3}, {%4,%5,%6,%7}, {%8,%9}, {%0,%1,%2,%3};"
        : "+f"(c[0]), "+f"(c[1]), "+f"(c[2]), "+f"(c[3])
        : "r"(a[0]), "r"(a[1]), "r"(a[2]), "r"(a[3]), "r"(b0), "r"(b1));
}

// ============ kernel 0: fused  x fp32->fp16 (k-permuted)  +  out=bias ============
// 4x ILP per thread.

static constexpr int CONV_BLOCKS = (M * K / 8) / (256 * 4);          // 64
static constexpr int INIT_BLOCKS = (M * N / 4 + 256 * 4 - 1) / (256 * 4); // 344

__global__ void prep_kernel(const float* __restrict__ x,
                            const float* __restrict__ bias,
                            float* __restrict__ out) {
    const int b = blockIdx.x;
    if (b < CONV_BLOCKS) {
        const int base = (b * 256 + threadIdx.x) * 4;   // 4 chunks of 8 floats
        float4 v[8];
        #pragma unroll
        for (int j = 0; j < 4; ++j) {
            const float4* s =
                reinterpret_cast<const float4*>(x) + (size_t)(base + j) * 2;
            v[2 * j]     = s[0];
            v[2 * j + 1] = s[1];
        }
        #pragma unroll
        for (int j = 0; j < 4; ++j) {
            uint4 o;
            __half2* o2 = reinterpret_cast<__half2*>(&o);
            o2[0] = __floats2half2_rn(v[2 * j].x, v[2 * j + 1].x);   // k 0,4
            o2[1] = __floats2half2_rn(v[2 * j].y, v[2 * j + 1].y);   // k 1,5
            o2[2] = __floats2half2_rn(v[2 * j].z, v[2 * j + 1].z);   // k 2,6
            o2[3] = __floats2half2_rn(v[2 * j].w, v[2 * j + 1].w);   // k 3,7
            reinterpret_cast<uint4*>(g_x16)[base + j] = o;
        }
    } else {
        const int base = ((b - CONV_BLOCKS) * 256 + threadIdx.x) * 4;
        #pragma unroll
        for (int j = 0; j < 4; ++j) {
            const int i = base + j;
            if (i < M * N / 4) {
                const float4 bv =
                    reinterpret_cast<const float4*>(bias)[i % (N / 4)];
                reinterpret_cast<float4*>(out)[i] = bv;
            }
        }
    }
}

// ======================= kernel 1: fused dequant + GEMM =======================
//
// CTA tile 128(m) x 256(n); 8 warps (2m x 4n), warp tile 64(m) x 64(n)
// (accum 128 regs/thread; 1 CTA/SM, reg ceiling 255 via launch_bounds(256,1)).
// Smem traffic per mma drops ~27% vs the 64x32 config — the crossbar was the
// measured binder, so the kernel flips to tensor-pipe-bound.
// A: [128 m][64 k] fp16 SW128 (k-permuted), cp.async, double-buffered.
// B: [256 n][64 k] fp16 SW128, lop3-dequantized (one n-column per thread,
//    8 packed rows), double-buffered.
// K split {22,22,20} stages. Grid 43 x 3 = 129 CTAs (single wave, 1/SM).
// Epilogue atomicAdd onto bias-preloaded out.

__global__ void __launch_bounds__(THREADS, 1)
quantlinear_kernel(
    const int*   __restrict__ qweight,  // [K/8, N] int32 (8 nibbles along K)
    const int*   __restrict__ qzeros,   // [G, N/8] int32 (8 nibbles along N)
    const float* __restrict__ scales,   // [G, N]
    float*       __restrict__ out       // [M, N], preloaded with bias
) {
    extern __shared__ __align__(1024) char smem_raw[];
    const uint32_t sb = (smem_u32(smem_raw) + 1023u) & ~1023u;

    const int tid  = threadIdx.x;
    const int wid  = tid >> 5;
    const int lane = tid & 31;
    const int mw   = wid >> 2;   // warp m index (0..1) -> rows mw*64
    const int nw   = wid & 3;    // warp n index (0..3) -> cols nw*64
    const int n0   = blockIdx.x * NTILE;
    const int kz   = blockIdx.y;

    // uneven K split: stage starts {0,22,44}, counts {22,22,20}
    const int stage0 = kz * 22;
    const int nst    = (kz == 2) ? 20 : 22;
    const int qrow0  = stage0 * 8;               // first packed qweight row
    const int g0     = stage0 >> 1;              // first quant group
    const int kbase0 = stage0 * KTILE;

    // ldmatrix per-thread invariant (unswizzled) byte offsets
    // A: warp rows mw*64 + (lane&15); frag mi at +mi*2048 (16 rows)
    const uint32_t aOff0 =
        (uint32_t)((mw * 64 + (lane & 15)) * 128 + (lane >> 4) * 16);
    // B: warp cols nw*64; x4 tile covers 16 n; tile nb at +nb*2048
    const uint32_t bOff0 =
        (uint32_t)((nw * 64 + ((lane >> 4) << 3) + (lane & 7)) * 128 +
                   ((lane >> 3) & 1) * 16);

    // B loader: one n-column per thread, 8 packed k-rows per stage
    const int gn = n0 + tid;

    float c[4][8][4];   // [mi 16m][j = 2*nb+p][frag] -> 128 accum regs
    #pragma unroll
    for (int i = 0; i < 4; ++i)
        #pragma unroll
        for (int j = 0; j < 8; ++j)
            #pragma unroll
            for (int l = 0; l < 4; ++l) c[i][j][l] = 0.f;

    uint32_t bw[8];
    __half2  s2, z2;

    // ---- stage helpers ----

    auto ISSUE_A = [&](int t, int buf) {
        const uint32_t abase = sb + (uint32_t)buf * A_BUF_STRIDE;
        const int kbase = kbase0 + t * KTILE;
        #pragma unroll
        for (int i = 0; i < 4; ++i) {
            const int cidx = tid + THREADS * i;   // 0..1023
            const int m  = cidx >> 3;             // 0..127
            const int ck = cidx & 7;              // 16B chunk in 128B row
            const uint32_t off = SWZ((uint32_t)(m * 128 + ck * 16));
            const __half* src = g_x16 + (size_t)m * K + kbase + ck * 8;
            CP_ASYNC16(abase + off, src);
        }
        CP_COMMIT();
    };

    auto LOAD_B = [&](int t) {
        if ((t & 1) == 0) {   // new quant group every 2 stages (GS=128)
            const int g = g0 + (t >> 1);
            const float s = scales[(size_t)g * N + gn];
            const uint32_t zw = (uint32_t)qzeros[(size_t)g * (N / 8) + (gn >> 3)];
            const uint32_t z = ((zw >> ((gn & 7) * 4)) & 0xFu) + 1u;
            s2 = __float2half2_rn(s);
            uint32_t zb = 0x64006400u + z + (z << 16);   // fp16x2 (1024+z), exact
            z2 = *reinterpret_cast<__half2*>(&zb);
        }
        #pragma unroll
        for (int r = 0; r < 8; ++r)
            bw[r] = (uint32_t)qweight[(size_t)(qrow0 + t * 8 + r) * N + gn];
    };

    auto DEQ_STS = [&](int buf) {
        const uint32_t bbase = sb + B_BASE_OFF + (uint32_t)buf * B_BUF_STRIDE;
        #pragma unroll
        for (int r = 0; r < 8; ++r) {
            const uint32_t w = bw[r];
            uint32_t o[4];
            // dual-nibble: pairs (k0,k4),(k1,k5),(k2,k6),(k3,k7) — matches
            // the permuted A layout.
            o[0] = lop3_nib(w);
            o[1] = lop3_nib(w >> 4);
            o[2] = lop3_nib(w >> 8);
            o[3] = lop3_nib(w >> 12);
            #pragma unroll
            for (int i = 0; i < 4; ++i) {
                __half2 q2 = *reinterpret_cast<__half2*>(&o[i]);
                __half2 w2 = __hmul2(__hsub2(q2, z2), s2);  // (q-z) exact
                o[i] = *reinterpret_cast<uint32_t*>(&w2);
            }
            const uint32_t off = SWZ((uint32_t)(tid * 128 + r * 16));
            STS128(bbase + off, o[0], o[1], o[2], o[3]);
        }
    };

    auto COMPUTE = [&](int buf) {
        const uint32_t abase = sb + (uint32_t)buf * A_BUF_STRIDE;
        const uint32_t bbase = sb + B_BASE_OFF + (uint32_t)buf * B_BUF_STRIDE;
        #pragma unroll
        for (int ks = 0; ks < 4; ++ks) {
            const uint32_t akb = (uint32_t)(ks * 32);
            uint32_t a[4][4];
            #pragma unroll
            for (int mi = 0; mi < 4; ++mi)
                ldsm4(a[mi], abase + SWZ(aOff0 + (uint32_t)(mi * 2048) + akb));
            #pragma unroll
            for (int nb = 0; nb < 4; ++nb) {
                uint32_t b[4];
                ldsm4(b, bbase + SWZ(bOff0 + (uint32_t)(nb * 2048) + akb));
                #pragma unroll
                for (int mi = 0; mi < 4; ++mi) {
                    mma16816(c[mi][2 * nb + 0], a[mi], b[0], b[1]);
                    mma16816(c[mi][2 * nb + 1], a[mi], b[2], b[3]);
                }
            }
        }
    };

    // -------- pipeline --------
    ISSUE_A(0, 0);
    LOAD_B(0);
    DEQ_STS(0);
    CP_WAIT0();
    __syncthreads();

    for (int t = 0; t < nst; ++t) {
        const int cur = t & 1;
        if (t + 1 < nst) {
            ISSUE_A(t + 1, cur ^ 1);
            LOAD_B(t + 1);
        }
        COMPUTE(cur);
        if (t + 1 < nst) {
            DEQ_STS(cur ^ 1);
            CP_WAIT0();
        }
        __syncthreads();
    }

    // -------- epilogue: atomic accumulate into out (bias preloaded) --------
    const int q  = lane >> 2;
    const int r2 = lane & 3;
    #pragma unroll
    for (int mi = 0; mi < 4; ++mi) {
        const int row0 = mw * 64 + mi * 16 + q;
        #pragma unroll
        for (int j = 0; j < 8; ++j) {
            const int col = n0 + nw * 64 + (j >> 1) * 16 + (j & 1) * 8 + 2 * r2;
            float* p0 = out + (size_t)row0 * N + col;
            float* p1 = out + (size_t)(row0 + 8) * N + col;
            atomicAdd(p0,     c[mi][j][0]);
            atomicAdd(p0 + 1, c[mi][j][1]);
            atomicAdd(p1,     c[mi][j][2]);
            atomicAdd(p1 + 1, c[mi][j][3]);
        }
    }
}

// ======================= launch =======================

extern "C" void kernel_launch(void* const* d_in, const int* in_sizes, int n_in,
                              void* d_out, int out_size) {
    const float* x       = (const float*)d_in[0];
    const int*   qweight = (const int*)d_in[1];
    const int*   qzeros  = (const int*)d_in[2];
    const float* scales  = (const float*)d_in[3];
    const float* bias    = (const float*)d_in[4];
    // d_in[5] = g_idx: arange(K)//128 for this problem; group = k/GS hardcoded.
    float* out = (float*)d_out;

    cudaFuncSetAttribute(quantlinear_kernel,
                         cudaFuncAttributeMaxDynamicSharedMemorySize, SMEM_BYTES);

    prep_kernel<<<CONV_BLOCKS + INIT_BLOCKS, 256>>>(x, bias, out);
    dim3 grid(NBLK_N, KSPLIT);
    quantlinear_kernel<<<grid, THREADS, SMEM_BYTES>>>(qweight, qzeros, scales, out);
}

// round 17
// speedup vs baseline: 1.2410x; 1.0256x over previous
#include <cuda_runtime.h>
#include <cuda_fp16.h>
#include <cstdint>

// ======================= problem constants =======================

static constexpr int M = 128;
static constexpr int K = 4096;
static constexpr int N = 11008;
static constexpr int NTILE = 256;           // output columns per CTA
static constexpr int KTILE = 128;           // K per pipeline stage (== GS)
static constexpr int KSPLIT = 3;            // uneven K thirds: 11/11/10 stages
static constexpr int THREADS = 256;         // 8 warps (2m x 4n), warp tile 64x64
static constexpr int NBLK_N = N / NTILE;    // 43

// SMEM (dynamic): A 2 bufs x 2 subtiles x 16KB ; B 2 bufs x 2 subtiles x 32KB
static constexpr uint32_t A_SUB_STRIDE = 16384;   // 128 m x 64 k fp16
static constexpr uint32_t A_BUF_STRIDE = 32768;
static constexpr uint32_t B_BASE_OFF   = 65536;
static constexpr uint32_t B_SUB_STRIDE = 32768;   // 256 n x 64 k fp16
static constexpr uint32_t B_BUF_STRIDE = 65536;
static constexpr uint32_t SMEM_BYTES   = 196608 + 1024;

// fp16 copy of x with k-chunk permutation {0,4,1,5,2,6,3,7} baked in
// (matches the lop3 dual-nibble extraction order of the B dequant path).
__device__ __half g_x16[M * K];

// ======================= small helpers =======================

__device__ __forceinline__ uint32_t smem_u32(const void* p) {
    uint32_t a;
    asm("{ .reg .u64 t; cvta.to.shared.u64 t, %1; cvt.u32.u64 %0, t; }"
        : "=r"(a) : "l"(p));
    return a;
}

// SW128 swizzle (Swizzle<3,4,3>): XOR bits [6:4] with bits [9:7]
#define SWZ(x) ((uint32_t)(x) ^ ((((uint32_t)(x)) >> 3) & 0x70u))

#define STS128(smem_addr, r0, r1, r2, r3) \
    asm volatile( \
        "st.shared.v4.b32 [%0], {%1, %2, %3, %4};" \
        :: "r"(smem_addr), "r"(r0), "r"(r1), "r"(r2), "r"(r3) \
        : "memory")

#define CP_ASYNC16(dst, src) \
    asm volatile("cp.async.ca.shared.global [%0], [%1], 16;" \
                 :: "r"(dst), "l"(src) : "memory")

#define CP_COMMIT()  asm volatile("cp.async.commit_group;" ::: "memory")
#define CP_WAIT0()   asm volatile("cp.async.wait_group 0;" ::: "memory")

// d = (a & 0x000F000F) | 0x64006400  -> fp16x2 (1024+q_lo, 1024+q_hi)
__device__ __forceinline__ uint32_t lop3_nib(uint32_t a) {
    uint32_t d;
    asm("lop3.b32 %0, %1, 0x000F000F, 0x64006400, 0xEA;" : "=r"(d) : "r"(a));
    return d;
}

__device__ __forceinline__ void ldsm4(uint32_t (&r)[4], uint32_t addr) {
    asm volatile(
        "ldmatrix.sync.aligned.m8n8.x4.shared.b16 {%0,%1,%2,%3}, [%4];"
        : "=r"(r[0]), "=r"(r[1]), "=r"(r[2]), "=r"(r[3])
        : "r"(addr));
}

__device__ __forceinline__ void mma16816(float (&c)[4], const uint32_t (&a)[4],
                                         uint32_t b0, uint32_t b1) {
    asm volatile(
        "mma.sync.aligned.m16n8k16.row.col.f32.f16.f16.f32 "
        "{%0,%1,%2,%3}, {%4,%5,%6,%7}, {%8,%9}, {%0,%1,%2,%3};"
        : "+f"(c[0]), "+f"(c[1]), "+f"(c[2]), "+f"(c[3])
        : "r"(a[0]), "r"(a[1]), "r"(a[2]), "r"(a[3]), "r"(b0), "r"(b1));
}

// ============ kernel 0: fused  x fp32->fp16 (k-permuted)  +  out=bias ============
// 4x ILP per thread.

static constexpr int CONV_BLOCKS = (M * K / 8) / (256 * 4);          // 64
static constexpr int INIT_BLOCKS = (M * N / 4 + 256 * 4 - 1) / (256 * 4); // 344

__global__ void prep_kernel(const float* __restrict__ x,
                            const float* __restrict__ bias,
                            float* __restrict__ out) {
    const int b = blockIdx.x;
    if (b < CONV_BLOCKS) {
        const int base = (b * 256 + threadIdx.x) * 4;   // 4 chunks of 8 floats
        float4 v[8];
        #pragma unroll
        for (int j = 0; j < 4; ++j) {
            const float4* s =
                reinterpret_cast<const float4*>(x) + (size_t)(base + j) * 2;
            v[2 * j]     = s[0];
            v[2 * j + 1] = s[1];
        }
        #pragma unroll
        for (int j = 0; j < 4; ++j) {
            uint4 o;
            __half2* o2 = reinterpret_cast<__half2*>(&o);
            o2[0] = __floats2half2_rn(v[2 * j].x, v[2 * j + 1].x);   // k 0,4
            o2[1] = __floats2half2_rn(v[2 * j].y, v[2 * j + 1].y);   // k 1,5
            o2[2] = __floats2half2_rn(v[2 * j].z, v[2 * j + 1].z);   // k 2,6
            o2[3] = __floats2half2_rn(v[2 * j].w, v[2 * j + 1].w);   // k 3,7
            reinterpret_cast<uint4*>(g_x16)[base + j] = o;
        }
    } else {
        const int base = ((b - CONV_BLOCKS) * 256 + threadIdx.x) * 4;
        #pragma unroll
        for (int j = 0; j < 4; ++j) {
            const int i = base + j;
            if (i < M * N / 4) {
                const float4 bv =
                    reinterpret_cast<const float4*>(bias)[i % (N / 4)];
                reinterpret_cast<float4*>(out)[i] = bv;
            }
        }
    }
}

// ======================= kernel 1: fused dequant + GEMM =======================
//
// CTA tile 128(m) x 256(n) x KTILE=128; 8 warps (2m x 4n), warp tile 64x64.
// KTILE doubled vs r16 to amortize the measured ~1750 cyc/stage fixed
// overhead (barrier join + producer tail + pipeline latency) over 2x the
// tensor work: stages per CTA drop 22 -> 11.
// A: [128 m][128 k] fp16, two SW128 64-k subtiles per buffer, cp.async,
//    double-buffered.
// B: [256 n][128 k] fp16, two SW128 subtiles, lop3-dequantized (one
//    n-column x 16 packed rows per thread), double-buffered.
// K split {11,11,10} stages of 128 (boundaries = group-aligned; KTILE==GS
// so scale/zero refresh once per stage).
// Grid 43 x 3 = 129 CTAs (single wave, 1 CTA/SM, 192KB smem).
// Epilogue atomicAdd onto bias-preloaded out.

__global__ void __launch_bounds__(THREADS, 1)
quantlinear_kernel(
    const int*   __restrict__ qweight,  // [K/8, N] int32 (8 nibbles along K)
    const int*   __restrict__ qzeros,   // [G, N/8] int32 (8 nibbles along N)
    const float* __restrict__ scales,   // [G, N]
    float*       __restrict__ out       // [M, N], preloaded with bias
) {
    extern __shared__ __align__(1024) char smem_raw[];
    const uint32_t sb = (smem_u32(smem_raw) + 1023u) & ~1023u;

    const int tid  = threadIdx.x;
    const int wid  = tid >> 5;
    const int lane = tid & 31;
    const int mw   = wid >> 2;   // warp m index (0..1) -> rows mw*64
    const int nw   = wid & 3;    // warp n index (0..3) -> cols nw*64
    const int n0   = blockIdx.x * NTILE;
    const int kz   = blockIdx.y;

    // uneven K split in 128-k stages: starts {0,11,22}, counts {11,11,10}
    const int stage0 = kz * 11;
    const int nst    = (kz == 2) ? 10 : 11;
    const int qrow0  = stage0 * 16;              // first packed qweight row
    const int g0     = stage0;                   // one group per stage
    const int kbase0 = stage0 * KTILE;

    // ldmatrix per-thread invariant (unswizzled) byte offsets (per subtile)
    const uint32_t aOff0 =
        (uint32_t)((mw * 64 + (lane & 15)) * 128 + (lane >> 4) * 16);
    const uint32_t bOff0 =
        (uint32_t)((nw * 64 + ((lane >> 4) << 3) + (lane & 7)) * 128 +
                   ((lane >> 3) & 1) * 16);

    // B loader: one n-column per thread, 16 packed k-rows per stage
    const int gn = n0 + tid;

    float c[4][8][4];   // [mi 16m][j = 2*nb+p][frag] -> 128 accum regs
    #pragma unroll
    for (int i = 0; i < 4; ++i)
        #pragma unroll
        for (int j = 0; j < 8; ++j)
            #pragma unroll
            for (int l = 0; l < 4; ++l) c[i][j][l] = 0.f;

    uint32_t bw[16];
    __half2  s2, z2;

    // ---- stage helpers ----

    auto ISSUE_A = [&](int t, int buf) {
        const uint32_t abase = sb + (uint32_t)buf * A_BUF_STRIDE;
        const int kbase = kbase0 + t * KTILE;
        #pragma unroll
        for (int i = 0; i < 8; ++i) {
            const int cidx = tid + THREADS * i;   // 0..2047
            const int m  = cidx >> 4;             // 0..127
            const int ck = cidx & 15;             // 16B chunk within 256B row
            const uint32_t sub = (uint32_t)(ck >> 3);
            const uint32_t off = SWZ((uint32_t)(m * 128 + (ck & 7) * 16));
            const __half* src = g_x16 + (size_t)m * K + kbase + ck * 8;
            CP_ASYNC16(abase + sub * A_SUB_STRIDE + off, src);
        }
        CP_COMMIT();
    };

    auto LOAD_B = [&](int t) {
        const int g = g0 + t;                    // KTILE == GS
        const float s = scales[(size_t)g * N + gn];
        const uint32_t zw = (uint32_t)qzeros[(size_t)g * (N / 8) + (gn >> 3)];
        const uint32_t z = ((zw >> ((gn & 7) * 4)) & 0xFu) + 1u;
        s2 = __float2half2_rn(s);
        uint32_t zb = 0x64006400u + z + (z << 16);   // fp16x2 (1024+z), exact
        z2 = *reinterpret_cast<__half2*>(&zb);
        #pragma unroll
        for (int r = 0; r < 16; ++r)
            bw[r] = (uint32_t)qweight[(size_t)(qrow0 + t * 16 + r) * N + gn];
    };

    auto DEQ_STS = [&](int buf) {
        const uint32_t bbase = sb + B_BASE_OFF + (uint32_t)buf * B_BUF_STRIDE;
        #pragma unroll
        for (int r = 0; r < 16; ++r) {
            const uint32_t w = bw[r];
            uint32_t o[4];
            // dual-nibble: pairs (k0,k4),(k1,k5),(k2,k6),(k3,k7) — matches
            // the permuted A layout.
            o[0] = lop3_nib(w);
            o[1] = lop3_nib(w >> 4);
            o[2] = lop3_nib(w >> 8);
            o[3] = lop3_nib(w >> 12);
            #pragma unroll
            for (int i = 0; i < 4; ++i) {
                __half2 q2 = *reinterpret_cast<__half2*>(&o[i]);
                __half2 w2 = __hmul2(__hsub2(q2, z2), s2);  // (q-z) exact
                o[i] = *reinterpret_cast<uint32_t*>(&w2);
            }
            const uint32_t sub = (uint32_t)(r >> 3);
            const uint32_t off = SWZ((uint32_t)(tid * 128 + (r & 7) * 16));
            STS128(bbase + sub * B_SUB_STRIDE + off, o[0], o[1], o[2], o[3]);
        }
    };

    auto COMPUTE = [&](int buf) {
        const uint32_t abase = sb + (uint32_t)buf * A_BUF_STRIDE;
        const uint32_t bbase = sb + B_BASE_OFF + (uint32_t)buf * B_BUF_STRIDE;
        #pragma unroll
        for (int ks = 0; ks < 8; ++ks) {
            const uint32_t asub = abase + (uint32_t)(ks >> 2) * A_SUB_STRIDE;
            const uint32_t bsub = bbase + (uint32_t)(ks >> 2) * B_SUB_STRIDE;
            const uint32_t akb  = (uint32_t)((ks & 3) * 32);
            uint32_t a[4][4];
            #pragma unroll
            for (int mi = 0; mi < 4; ++mi)
                ldsm4(a[mi], asub + SWZ(aOff0 + (uint32_t)(mi * 2048) + akb));
            #pragma unroll
            for (int nb = 0; nb < 4; ++nb) {
                uint32_t b[4];
                ldsm4(b, bsub + SWZ(bOff0 + (uint32_t)(nb * 2048) + akb));
                #pragma unroll
                for (int mi = 0; mi < 4; ++mi) {
                    mma16816(c[mi][2 * nb + 0], a[mi], b[0], b[1]);
                    mma16816(c[mi][2 * nb + 1], a[mi], b[2], b[3]);
                }
            }
        }
    };

    // -------- pipeline --------
    ISSUE_A(0, 0);
    LOAD_B(0);
    DEQ_STS(0);
    CP_WAIT0();
    __syncthreads();

    for (int t = 0; t < nst; ++t) {
        const int cur = t & 1;
        if (t + 1 < nst) {
            ISSUE_A(t + 1, cur ^ 1);
            LOAD_B(t + 1);
        }
        COMPUTE(cur);
        if (t + 1 < nst) {
            DEQ_STS(cur ^ 1);
            CP_WAIT0();
        }
        __syncthreads();
    }

    // -------- epilogue: atomic accumulate into out (bias preloaded) --------
    const int q  = lane >> 2;
    const int r2 = lane & 3;
    #pragma unroll
    for (int mi = 0; mi < 4; ++mi) {
        const int row0 = mw * 64 + mi * 16 + q;
        #pragma unroll
        for (int j = 0; j < 8; ++j) {
            const int col = n0 + nw * 64 + (j >> 1) * 16 + (j & 1) * 8 + 2 * r2;
            float* p0 = out + (size_t)row0 * N + col;
            float* p1 = out + (size_t)(row0 + 8) * N + col;
            atomicAdd(p0,     c[mi][j][0]);
            atomicAdd(p0 + 1, c[mi][j][1]);
            atomicAdd(p1,     c[mi][j][2]);
            atomicAdd(p1 + 1, c[mi][j][3]);
        }
    }
}

// ======================= launch =======================

extern "C" void kernel_launch(void* const* d_in, const int* in_sizes, int n_in,
                              void* d_out, int out_size) {
    const float* x       = (const float*)d_in[0];
    const int*   qweight = (const int*)d_in[1];
    const int*   qzeros  = (const int*)d_in[2];
    const float* scales  = (const float*)d_in[3];
    const float* bias    = (const float*)d_in[4];
    // d_in[5] = g_idx: arange(K)//128 for this problem; group = k/GS hardcoded.
    float* out = (float*)d_out;

    cudaFuncSetAttribute(quantlinear_kernel,
                         cudaFuncAttributeMaxDynamicSharedMemorySize, SMEM_BYTES);

    prep_kernel<<<CONV_BLOCKS + INIT_BLOCKS, 256>>>(x, bias, out);
    dim3 grid(NBLK_N, KSPLIT);
    quantlinear_kernel<<<grid, THREADS, SMEM_BYTES>>>(qweight, qzeros, scales, out);
}